// round 10
// baseline (speedup 1.0000x reference)
#include <cuda_runtime.h>
#include <cstdint>

#define BATCH       8192
#define FEAT_DIM    2048
#define NUM_CLASSES 751
#define TPB         256
#define NBLK        888                      // 6 CTAs/SM * 148 SMs
#define ROW_F4      (FEAT_DIM / 4)           // 512 float4 per row
#define ROW_BYTES   (FEAT_DIM * 4)           // 8192
#define STAGE_BYTES (2 * ROW_BYTES)          // x row + c row = 16384

__device__ float        g_partial[NBLK];
__device__ unsigned int g_done_count;        // zero at load; last block resets

__device__ __forceinline__ unsigned smem_u32(const void* p) {
    unsigned a;
    asm("{ .reg .u64 t; cvta.to.shared.u64 t, %1; cvt.u32.u64 %0, t; }"
        : "=r"(a) : "l"(p));
    return a;
}
__device__ __forceinline__ void mbar_init(unsigned mbar, unsigned cnt) {
    asm volatile("mbarrier.init.shared.b64 [%0], %1;" :: "r"(mbar), "r"(cnt) : "memory");
}
__device__ __forceinline__ void mbar_arrive(unsigned mbar) {
    asm volatile("mbarrier.arrive.release.cta.shared::cta.b64 _, [%0];"
                 :: "r"(mbar) : "memory");
}
__device__ __forceinline__ void mbar_expect_tx(unsigned mbar, unsigned bytes) {
    asm volatile("mbarrier.arrive.expect_tx.shared.b64 _, [%0], %1;"
                 :: "r"(mbar), "r"(bytes) : "memory");
}
__device__ __forceinline__ void mbar_wait(unsigned mbar, unsigned phase) {
    asm volatile(
        "{\n\t"
        ".reg .pred P;\n\t"
        "WL_%=:\n\t"
        "mbarrier.try_wait.parity.acquire.cta.shared::cta.b64 P, [%0], %1, 0x989680;\n\t"
        "@P bra.uni WD_%=;\n\t"
        "bra.uni WL_%=;\n\t"
        "WD_%=:\n\t"
        "}" :: "r"(mbar), "r"(phase) : "memory");
}
__device__ __forceinline__ void bulk_copy_g2s(unsigned smem_dst, const void* gmem_src,
                                              unsigned bytes, unsigned mbar) {
    asm volatile(
        "cp.async.bulk.shared::cta.global.mbarrier::complete_tx::bytes [%0], [%1], %2, [%3];"
        :: "r"(smem_dst), "l"(gmem_src), "r"(bytes), "r"(mbar) : "memory");
}

__global__ void __launch_bounds__(TPB, 6)
center_loss_kernel(const float* __restrict__ x,
                   const int*   __restrict__ labels_i32,
                   const float* __restrict__ centers,
                   float*       __restrict__ out) {
    // 2 stages x (x row | c row), 16 KB each -> 32 KB data + barriers
    __shared__ alignas(128) float4   s_x[2][ROW_F4];
    __shared__ alignas(128) float4   s_c[2][ROW_F4];
    __shared__ alignas(8)   uint64_t s_full[2], s_empty[2];

    const int tid  = threadIdx.x;
    const int lane = tid & 31;
    const int wid  = tid >> 5;
    const int bid  = blockIdx.x;

    const unsigned fb0 = smem_u32(&s_full[0]),  fb1 = smem_u32(&s_full[1]);
    const unsigned eb0 = smem_u32(&s_empty[0]), eb1 = smem_u32(&s_empty[1]);

    // labels width detection: only the producer warp needs it
    int lblshift = 0;
    if (wid == 0) {
        // int64 LE: odd int32 words of first 16 pairs (labels in [0,751)) are 0
        int hiw = (lane < 16) ? __ldg(labels_i32 + 2 * lane + 1) : 0;
        lblshift = (__ballot_sync(0xFFFFFFFFu, hiw != 0) == 0u) ? 1 : 0;
    }

    if (tid == 0) {
        mbar_init(fb0, 1);   mbar_init(fb1, 1);    // completed by expect_tx + tx bytes
        mbar_init(eb0, TPB); mbar_init(eb1, TPB);  // completed by 256 consumer arrivals
    }
    __syncthreads();

    // tiles for this block: rows bid, bid+NBLK, ... (fixed order)
    const int nt = (BATCH - 1 - bid) / NBLK + 1;

    // ---- prologue: producer fills both stages ----
    if (tid == 0) {
        {
            const int row = bid;
            const int lbl = __ldg(labels_i32 + (row << lblshift));
            mbar_expect_tx(fb0, STAGE_BYTES);
            bulk_copy_g2s(smem_u32(&s_x[0][0]), x + (size_t)row * FEAT_DIM, ROW_BYTES, fb0);
            bulk_copy_g2s(smem_u32(&s_c[0][0]), centers + (size_t)lbl * FEAT_DIM, ROW_BYTES, fb0);
        }
        if (nt > 1) {
            const int row = bid + NBLK;
            const int lbl = __ldg(labels_i32 + (row << lblshift));
            mbar_expect_tx(fb1, STAGE_BYTES);
            bulk_copy_g2s(smem_u32(&s_x[1][0]), x + (size_t)row * FEAT_DIM, ROW_BYTES, fb1);
            bulk_copy_g2s(smem_u32(&s_c[1][0]), centers + (size_t)lbl * FEAT_DIM, ROW_BYTES, fb1);
        }
    }

    float acc = 0.0f;
    int ph_f0 = 0, ph_f1 = 0, ph_e0 = 0, ph_e1 = 0;

    #define TILE_STEP(S, FB, EB, PHF, PHE)                                     \
        {                                                                      \
            mbar_wait((FB), (PHF)); (PHF) ^= 1;                                \
            float4 a0 = s_x[S][tid];                                           \
            float4 a1 = s_x[S][tid + TPB];                                     \
            float4 c0 = s_c[S][tid];                                           \
            float4 c1 = s_c[S][tid + TPB];                                     \
            float d;                                                           \
            d = a0.x - c0.x; acc += d * d;  d = a0.y - c0.y; acc += d * d;     \
            d = a0.z - c0.z; acc += d * d;  d = a0.w - c0.w; acc += d * d;     \
            d = a1.x - c1.x; acc += d * d;  d = a1.y - c1.y; acc += d * d;     \
            d = a1.z - c1.z; acc += d * d;  d = a1.w - c1.w; acc += d * d;     \
            mbar_arrive((EB));                                                 \
            if (tid == 0 && k + 2 < nt) {                                      \
                mbar_wait((EB), (PHE)); (PHE) ^= 1;                            \
                const int _row = bid + (k + 2) * NBLK;                         \
                const int _lbl = __ldg(labels_i32 + (_row << lblshift));       \
                mbar_expect_tx((FB), STAGE_BYTES);                             \
                bulk_copy_g2s(smem_u32(&s_x[S][0]),                            \
                              x + (size_t)_row * FEAT_DIM, ROW_BYTES, (FB));   \
                bulk_copy_g2s(smem_u32(&s_c[S][0]),                            \
                              centers + (size_t)_lbl * FEAT_DIM, ROW_BYTES, (FB)); \
            }                                                                  \
        }

    int k = 0;
    while (k < nt) {
        TILE_STEP(0, fb0, eb0, ph_f0, ph_e0)
        k++;
        if (k >= nt) break;
        TILE_STEP(1, fb1, eb1, ph_f1, ph_e1)
        k++;
    }
    #undef TILE_STEP

    // ---- single end-of-kernel reduction (fixed order -> deterministic) ----
    // clamp(d,1e-12,1e12) is inert (row distances ~4096): global sum of
    // squared diffs equals the sum of clamped per-row sums.
    #pragma unroll
    for (int off = 16; off > 0; off >>= 1)
        acc += __shfl_xor_sync(0xFFFFFFFFu, acc, off);

    __shared__ float s_w[TPB / 32];
    if (lane == 0) s_w[wid] = acc;
    __syncthreads();

    __shared__ bool s_is_last;
    if (tid == 0) {
        float p = 0.0f;
        #pragma unroll
        for (int w = 0; w < TPB / 32; w++) p += s_w[w];
        g_partial[bid] = p;
        unsigned int prev;
        asm volatile("atom.acq_rel.gpu.global.add.u32 %0, [%1], %2;"
                     : "=r"(prev)
                     : "l"(&g_done_count), "r"(1u)
                     : "memory");
        s_is_last = (prev == (unsigned int)(NBLK - 1));
    }
    __syncthreads();

    if (s_is_last) {
        float lacc = 0.0f;
        for (int j = tid; j < NBLK; j += TPB)       // fixed order per thread
            lacc += __ldcg(&g_partial[j]);

        #pragma unroll
        for (int off = 16; off > 0; off >>= 1)
            lacc += __shfl_xor_sync(0xFFFFFFFFu, lacc, off);

        __shared__ float s_fin[TPB / 32];
        if (lane == 0) s_fin[wid] = lacc;
        __syncthreads();

        if (tid == 0) {
            float total = 0.0f;
            #pragma unroll
            for (int w = 0; w < TPB / 32; w++) total += s_fin[w];
            const float clipped_zeros =
                (float)BATCH * (float)(NUM_CLASSES - 1) * 1e-12f;
            out[0] = (total + clipped_zeros) / (float)BATCH;
            g_done_count = 0;                        // reset for graph replay
        }
    }
}

extern "C" void kernel_launch(void* const* d_in, const int* in_sizes, int n_in,
                              void* d_out, int out_size) {
    const float* x       = (const float*)d_in[0];
    const int*   labels  = (const int*)d_in[1];   // width detected in-kernel
    const float* centers = (const float*)d_in[2];
    float*       out     = (float*)d_out;

    center_loss_kernel<<<NBLK, TPB>>>(x, labels, centers, out);
}